// round 14
// baseline (speedup 1.0000x reference)
#include <cuda_runtime.h>
#include <cuda_bf16.h>

// Problem constants
#define NWALK 4096
#define NIN   24      // NPART*NDIM = 8*3
#define HID   256
#define TPB   128             // 4 warps
#define WPB   8               // walkers per block (2 per warp, one per half-warp)
#define COLP  28              // padded column stride (floats): 16B-aligned, odd/4 -> <=2-way conflicts
#define NCHUNK (HID / 16)     // 16 hidden units per lane

// out[w] = -1/2 * ( lap log|psi| + |grad log|psi||^2 ) for
// log|psi|(z) = W2 . tanh(z W1 + b1) + b2
//
// Closed form:
//   a_j = sum_i z_i W1[i,j] + b1_j ; h_j = tanh(a_j) ; t_j = (1-h_j^2) W2_j
//   grad_i = sum_j W1[i,j] t_j
//   lap    = sum_j (-2 h_j t_j) * S_j,  S_j = sum_i W1[i,j]^2
//
// Mapping: half-warp per walker; lane sublane s owns hidden units j = s + 16*k.
// W1 stored column-major (padded to 28 floats) -> 6x LDS.128 per column.
// (b1, W2, S) packed into one float4 per column -> 1x LDS.128.
__global__ __launch_bounds__(TPB, 4)
void kinetic_kernel(const float* __restrict__ x,
                    const float* __restrict__ W1,
                    const float* __restrict__ b1,
                    const float* __restrict__ W2,
                    float* __restrict__ out)
{
    __shared__ float  sW1t[HID * COLP];   // 28 KB, column j at sW1t + j*28
    __shared__ float4 sMeta[HID];         // {b1, W2, S, 0}
    __shared__ float  sX[WPB][NIN];       // rows are 96B = 16B-aligned

    const int t = threadIdx.x;

    // ---- transpose W1 into column-major shared (coalesced gmem reads) ----
#pragma unroll
    for (int i = 0; i < NIN; i++) {
        sW1t[(t +   0) * COLP + i] = W1[i * HID + t];
        sW1t[(t + 128) * COLP + i] = W1[i * HID + t + 128];
    }
    {
        int base = blockIdx.x * (WPB * NIN);
        // WPB*NIN = 192 > TPB = 128: MUST stride (R8 bug: guarded single store
        // left elements 128..191 uninitialized)
        for (int e = t; e < WPB * NIN; e += TPB)
            sX[e / NIN][e % NIN] = x[base + e];
    }
    __syncthreads();

    // ---- meta[j] = {b1[j], W2[j], S_j, 0};  S_j = sum_i W1[i,j]^2 ----
#pragma unroll
    for (int rep = 0; rep < 2; rep++) {
        const int j = t + rep * 128;
        const float4* col = reinterpret_cast<const float4*>(&sW1t[j * COLP]);
        float s0 = 0.f, s1 = 0.f, s2 = 0.f, s3 = 0.f;
#pragma unroll
        for (int m = 0; m < 6; m++) {
            float4 v = col[m];
            s0 = fmaf(v.x, v.x, s0);
            s1 = fmaf(v.y, v.y, s1);
            s2 = fmaf(v.z, v.z, s2);
            s3 = fmaf(v.w, v.w, s3);
        }
        sMeta[j] = make_float4(b1[j], W2[j], (s0 + s1) + (s2 + s3), 0.f);
    }
    __syncthreads();

    const int warp = t >> 5;
    const int lane = t & 31;
    const int half = lane >> 4;      // walker within the warp
    const int s    = lane & 15;      // sublane within half-warp
    const int wkr  = warp * 2 + half;

    // walker coordinates (vectorized broadcast LDS -> registers)
    float z[NIN];
    {
        const float4* zx = reinterpret_cast<const float4*>(sX[wkr]);
#pragma unroll
        for (int m = 0; m < 6; m++) {
            float4 v = zx[m];
            z[4*m+0] = v.x; z[4*m+1] = v.y; z[4*m+2] = v.z; z[4*m+3] = v.w;
        }
    }

    float g[NIN];
#pragma unroll
    for (int i = 0; i < NIN; i++) g[i] = 0.f;
    float lap = 0.f;

    // Each lane owns 16 hidden units: j = s + 16*k
    for (int k = 0; k < NCHUNK; k++) {
        const int j = s + 16 * k;

        // W1 column: 6x LDS.128 (reused for 'a' pass and 'g' pass)
        float w[NIN];
        {
            const float4* col = reinterpret_cast<const float4*>(&sW1t[j * COLP]);
#pragma unroll
            for (int m = 0; m < 6; m++) {
                float4 v = col[m];
                w[4*m+0] = v.x; w[4*m+1] = v.y; w[4*m+2] = v.z; w[4*m+3] = v.w;
            }
        }
        float4 meta = sMeta[j];

        // a_j with 4 split accumulators (break the RAW chain)
        float a0 = 0.f, a1 = 0.f, a2 = 0.f, a3 = 0.f;
#pragma unroll
        for (int i = 0; i < NIN; i += 4) {
            a0 = fmaf(z[i + 0], w[i + 0], a0);
            a1 = fmaf(z[i + 1], w[i + 1], a1);
            a2 = fmaf(z[i + 2], w[i + 2], a2);
            a3 = fmaf(z[i + 3], w[i + 3], a3);
        }
        float a = ((a0 + a1) + (a2 + a3)) + meta.x;

        // accurate tanh via expf (MUFU EX2-based, ~1e-6 rel err)
        float e  = __expf(-2.0f * fabsf(a));
        float h  = __fdividef(1.0f - e, 1.0f + e);
        h = copysignf(h, a);

        float tj = (1.0f - h * h) * meta.y;
        lap = fmaf(-2.0f * h * tj, meta.z, lap);

#pragma unroll
        for (int i = 0; i < NIN; i++)
            g[i] = fmaf(w[i], tj, g[i]);
    }

    // ---- reduce-scatter over the half-warp (recursive halving) ----
    // xor8: 24 -> 12
    {
        const bool kl = (s & 8) == 0;
#pragma unroll
        for (int i = 0; i < 12; i++) {
            float snd = kl ? g[i + 12] : g[i];
            float kp  = kl ? g[i]      : g[i + 12];
            g[i] = kp + __shfl_xor_sync(0xffffffffu, snd, 8);
        }
    }
    // xor4: 12 -> 6
    {
        const bool kl = (s & 4) == 0;
#pragma unroll
        for (int i = 0; i < 6; i++) {
            float snd = kl ? g[i + 6] : g[i];
            float kp  = kl ? g[i]     : g[i + 6];
            g[i] = kp + __shfl_xor_sync(0xffffffffu, snd, 4);
        }
    }
    // xor2: 6 -> 3
    {
        const bool kl = (s & 2) == 0;
#pragma unroll
        for (int i = 0; i < 3; i++) {
            float snd = kl ? g[i + 3] : g[i];
            float kp  = kl ? g[i]     : g[i + 3];
            g[i] = kp + __shfl_xor_sync(0xffffffffu, snd, 2);
        }
    }
    // xor1: plain butterfly on the remaining 3 (both pair lanes end with full sums)
#pragma unroll
    for (int i = 0; i < 3; i++)
        g[i] += __shfl_xor_sync(0xffffffffu, g[i], 1);

    // each 3-component block is now held (fully reduced) by exactly 2 lanes
    float gsq = fmaf(g[0], g[0], fmaf(g[1], g[1], g[2] * g[2])); // double-counted

    // final scalar reduction over the half-warp
#pragma unroll
    for (int off = 8; off; off >>= 1) {
        lap += __shfl_xor_sync(0xffffffffu, lap, off);
        gsq += __shfl_xor_sync(0xffffffffu, gsq, off);
    }

    if (s == 0)
        out[blockIdx.x * WPB + wkr] = -0.5f * (lap + 0.5f * gsq);
}

extern "C" void kernel_launch(void* const* d_in, const int* in_sizes, int n_in,
                              void* d_out, int out_size)
{
    const float* x  = (const float*)d_in[0];
    const float* W1 = (const float*)d_in[1];
    const float* b1 = (const float*)d_in[2];
    const float* W2 = (const float*)d_in[3];
    // d_in[4] = b2 : no effect on derivatives
    float* out = (float*)d_out;

    kinetic_kernel<<<NWALK / WPB, TPB>>>(x, W1, b1, W2, out);
}